// round 5
// baseline (speedup 1.0000x reference)
#include <cuda_runtime.h>
#include <cuda_fp16.h>
#include <cooperative_groups.h>

namespace cg = cooperative_groups;

#define BB 256
#define TT 2048
#define DD 40
#define HH 128
#define CC 35

// A-operand row stride (halves): 528B; 528 mod 128 = 16 -> conflict-free ldmatrix.
#define AK 264
#define KT0 11   // layer0: [x(40)->48 | h1(128)] K=176
#define KT1 16   // layer1: [h1(128) | h2(128)]   K=256

__device__ int   g_order[BB];
__device__ int   g_slen[BB];
__device__ float g_h2[BB * HH];

// ---------------- mma / ldsm ----------------
__device__ __forceinline__ void mma16816(float* d, const unsigned* a, const unsigned* b) {
    asm volatile(
        "mma.sync.aligned.m16n8k16.row.col.f32.f16.f16.f32 "
        "{%0,%1,%2,%3}, {%4,%5,%6,%7}, {%8,%9}, {%0,%1,%2,%3};\n"
        : "+f"(d[0]), "+f"(d[1]), "+f"(d[2]), "+f"(d[3])
        : "r"(a[0]), "r"(a[1]), "r"(a[2]), "r"(a[3]), "r"(b[0]), "r"(b[1]));
}
__device__ __forceinline__ void ldsmx4(unsigned* a, const __half* p) {
    unsigned addr = (unsigned)__cvta_generic_to_shared(p);
    asm volatile("ldmatrix.sync.aligned.m8n8.x4.shared.b16 {%0,%1,%2,%3}, [%4];"
                 : "=r"(a[0]), "=r"(a[1]), "=r"(a[2]), "=r"(a[3])
                 : "r"(addr));
}
__device__ __forceinline__ float sigf(float x)   { return 1.0f / (1.0f + __expf(-x)); }
__device__ __forceinline__ float tanhfa(float x) { return 1.0f - 2.0f / (__expf(2.0f * x) + 1.0f); }

// ---------------- mbarrier helpers (cluster scope) ----------------
__device__ __forceinline__ void mbar_init(unsigned addr, unsigned cnt) {
    asm volatile("mbarrier.init.shared.b64 [%0], %1;" :: "r"(addr), "r"(cnt) : "memory");
}
__device__ __forceinline__ void mbar_arrive_remote(unsigned local_addr, unsigned rank) {
    asm volatile("{\n\t.reg .b32 ra;\n\t"
                 "mapa.shared::cluster.u32 ra, %0, %1;\n\t"
                 "mbarrier.arrive.release.cluster.shared::cluster.b64 _, [ra];\n\t}"
                 :: "r"(local_addr), "r"(rank) : "memory");
}
__device__ __forceinline__ void mbar_wait(unsigned addr, unsigned parity) {
    asm volatile("{\n\t.reg .pred P;\n"
                 "WAIT_%=:\n\t"
                 "mbarrier.try_wait.parity.acquire.cluster.shared::cta.b64 P, [%0], %1;\n\t"
                 "@!P bra WAIT_%=;\n\t}"
                 :: "r"(addr), "r"(parity) : "memory");
}

// ---------------- K0: rank-sort lengths (descending, stable) ----------------
__global__ void sort_kernel(const int* __restrict__ length) {
    __shared__ int len[BB];
    int i = threadIdx.x;
    len[i] = length[i];
    __syncthreads();
    int li = len[i];
    int rank = 0;
    for (int j = 0; j < BB; ++j) {
        int lj = len[j];
        rank += (lj > li) || (lj == li && j < i);
    }
    g_order[rank] = i;
    g_slen[rank]  = li;
}

// ---------------- K1: fused 2-layer LSTM, mbarrier pipeline ----------------
__global__ void __cluster_dims__(8, 1, 1) __launch_bounds__(256, 1)
lstm_fused(const float* __restrict__ x,
           const float* __restrict__ Wih0, const float* __restrict__ Whh0,
           const float* __restrict__ bih0, const float* __restrict__ bhh0,
           const float* __restrict__ Wih1, const float* __restrict__ Whh1,
           const float* __restrict__ bih1, const float* __restrict__ bhh1)
{
    cg::cluster_group cl = cg::this_cluster();
    const int rank   = (int)cl.block_rank();
    const bool is_l0 = (rank < 4);
    const int lrank  = rank & 3;
    const int group  = blockIdx.x >> 3;
    const int slotbase = group * 16;
    const int tid  = threadIdx.x;
    const int warp = tid >> 5, lane = tid & 31;

    __shared__ __align__(16) __half Ab[2][16][AK];
    __shared__ __align__(16) __half hstage[16][32];
    __shared__ float bsm[128];
    __shared__ int   slenS[16], morder[16];
    __shared__ unsigned long long mb_full[2], mb_ok[2];

    // ---- weights -> register fragments (gate-interleaved columns) ----
    const float* Wih = is_l0 ? Wih0 : Wih1;
    const float* Whh = is_l0 ? Whh0 : Whh1;
    const float* bih = is_l0 ? bih0 : bih1;
    const float* bhh = is_l0 ? bhh0 : bhh1;
    const int KX  = is_l0 ? 48 : 128;
    const int DIN = is_l0 ? DD : HH;

    unsigned wf[2][16][2];
#pragma unroll
    for (int nt = 0; nt < 2; ++nt) {
        int n_local = warp * 16 + nt * 8 + (lane >> 2);
        int grow = (n_local & 3) * 128 + lrank * 32 + (n_local >> 2);
        for (int kt = 0; kt < 16; ++kt) {
            if (kt >= (is_l0 ? KT0 : KT1)) break;
#pragma unroll
            for (int f = 0; f < 2; ++f) {
                int k0 = kt * 16 + (lane & 3) * 2 + f * 8;
                int k1 = k0 + 1;
                float v0 = (k0 < KX) ? ((k0 < DIN) ? Wih[grow * DIN + k0] : 0.0f)
                                     : Whh[grow * HH + (k0 - KX)];
                float v1 = (k1 < KX) ? ((k1 < DIN) ? Wih[grow * DIN + k1] : 0.0f)
                                     : Whh[grow * HH + (k1 - KX)];
                __half2 hv = __floats2half2_rn(v0, v1);
                wf[nt][kt][f] = *reinterpret_cast<unsigned*>(&hv);
            }
        }
    }
    if (tid < 128) {
        int grow = (tid & 3) * 128 + lrank * 32 + (tid >> 2);
        bsm[tid] = bih[grow] + bhh[grow];
    }
    if (tid < 16) {
        slenS[tid]  = g_slen[slotbase + tid];
        morder[tid] = g_order[slotbase + tid];
    }
    for (int i = tid; i < 2 * 16 * AK; i += 256) ((__half*)Ab)[i] = __float2half(0.0f);

    const unsigned cnt_full = is_l0 ? 4u : 8u;   // producers arriving on my full[]
    const unsigned cnt_ok   = is_l0 ? 8u : 4u;   // consumers arriving on my ok[]
    unsigned fullA[2], okA[2];
    fullA[0] = (unsigned)__cvta_generic_to_shared(&mb_full[0]);
    fullA[1] = (unsigned)__cvta_generic_to_shared(&mb_full[1]);
    okA[0]   = (unsigned)__cvta_generic_to_shared(&mb_ok[0]);
    okA[1]   = (unsigned)__cvta_generic_to_shared(&mb_ok[1]);
    if (tid == 0) {
        mbar_init(fullA[0], cnt_full); mbar_init(fullA[1], cnt_full);
        mbar_init(okA[0],   cnt_ok);   mbar_init(okA[1],   cnt_ok);
    }
    __syncthreads();
    const int maxlen = slenS[0];

    // per-thread cell ownership
    const int m_row = (lane >> 2) + ((lane & 1) << 3);
    const int myslen = slenS[m_row];
    const int hj0 = (warp << 2) + ((lane & 3) >> 1);
    const int hj1 = hj0 + 2;
    float creg[2] = {0.0f, 0.0f};
    float hreg[2] = {0.0f, 0.0f};
    unsigned ph_full[2] = {0u, 0u}, ph_ok[2] = {0u, 0u};

    // x prefetch thread-constant addressing
    const int i0 = tid, i1 = tid + 256, i2 = tid + 512;
    const float *px0 = nullptr, *px1 = nullptr, *px2 = nullptr;
    int so0 = 0, so1 = 0, so2 = 0;
    if (is_l0) {
        int m0 = i0 / DD, d0 = i0 - m0 * DD;
        int m1 = i1 / DD, d1 = i1 - m1 * DD;
        px0 = x + (size_t)morder[m0] * TT * DD + d0 + DD;   // points at x(s+1)
        px1 = x + (size_t)morder[m1] * TT * DD + d1 + DD;
        so0 = m0 * AK + d0; so1 = m1 * AK + d1;
        if (i2 < 16 * DD) {
            int m2 = i2 / DD, d2 = i2 - m2 * DD;
            px2 = x + (size_t)morder[m2] * TT * DD + d2 + DD;
            so2 = m2 * AK + d2;
        }
        // x(0) -> buffer 0
        for (int i = tid; i < 16 * DD; i += 256) {
            int m = i / DD, d = i - m * DD;
            Ab[0][m][d] = __float2half(x[((size_t)morder[m] * TT) * DD + d]);
        }
    }
    cl.sync();   // mbarrier init + buffer0 visible cluster-wide

    const int nprod = is_l0 ? 4 : 8;   // my producers (ok targets)
    const bool writer = is_l0 || warp >= 4;
    const int doff = (warp < 4) ? (48 + lrank * 32)
                                : ((is_l0 ? 0 : 128) + lrank * 32);

    for (int s = 0; s <= maxlen; ++s) {
        const int p = s & 1, pn = p ^ 1;
        const bool compute = is_l0 ? (s < maxlen) : (s >= 1);
        const bool do_pref = is_l0 && (s + 1 < maxlen);

        // issue x(s+1) loads early
        float xv0 = 0.0f, xv1 = 0.0f, xv2 = 0.0f;
        if (do_pref) {
            xv0 = *px0; xv1 = *px1;
            if (px2) xv2 = *px2;
            px0 += DD; px1 += DD; if (px2) px2 += DD;
        }

        // wait for producers of buffer p (h slices written during s-1)
        if (compute && s >= 1) { mbar_wait(fullA[p], ph_full[p]); ph_full[p] ^= 1; }

        if (compute) {
            float acc[2][4];
            int cb0 = warp * 16 + 2 * (lane & 3);
#pragma unroll
            for (int nt = 0; nt < 2; ++nt) {
                float b0 = bsm[cb0 + nt * 8], b1 = bsm[cb0 + nt * 8 + 1];
                acc[nt][0] = b0; acc[nt][1] = b1; acc[nt][2] = b0; acc[nt][3] = b1;
            }
            const __half* arow = &Ab[p][lane & 15][(lane >> 4) << 3];
            if (is_l0) {
#pragma unroll
                for (int kt = 0; kt < KT0; ++kt) {
                    unsigned a[4];
                    ldsmx4(a, arow + kt * 16);
                    mma16816(acc[0], a, wf[0][kt]);
                    mma16816(acc[1], a, wf[1][kt]);
                }
            } else {
#pragma unroll
                for (int kt = 0; kt < KT1; ++kt) {
                    unsigned a[4];
                    ldsmx4(a, arow + kt * 16);
                    mma16816(acc[0], a, wf[0][kt]);
                    mma16816(acc[1], a, wf[1][kt]);
                }
            }
            const int t_eff = is_l0 ? s : (s - 1);
            const bool act = t_eff < myslen;
            const int sel = (lane & 1) * 2;
#pragma unroll
            for (int nt = 0; nt < 2; ++nt) {
                float o0 = __shfl_xor_sync(0xffffffffu, acc[nt][0], 1);
                float o1 = __shfl_xor_sync(0xffffffffu, acc[nt][1], 1);
                float o2 = __shfl_xor_sync(0xffffffffu, acc[nt][2], 1);
                float o3 = __shfl_xor_sync(0xffffffffu, acc[nt][3], 1);
                float iv, fv, gv, ov;
                if ((lane & 1) == 0) {
                    iv = acc[nt][sel]; fv = acc[nt][sel + 1];
                    gv = (sel == 0) ? o0 : o2; ov = (sel == 0) ? o1 : o3;
                } else {
                    iv = (sel == 0) ? o0 : o2; fv = (sel == 0) ? o1 : o3;
                    gv = acc[nt][sel]; ov = acc[nt][sel + 1];
                }
                float hn;
                if (act) {
                    float gi = sigf(iv), gf = sigf(fv), gg = tanhfa(gv), go = sigf(ov);
                    float cn = gf * creg[nt] + gi * gg;
                    creg[nt] = cn;
                    hn = go * tanhfa(cn);
                    hreg[nt] = hn;
                } else {
                    hn = hreg[nt];
                }
                hstage[m_row][nt ? hj1 : hj0] = __float2half(hn);
            }
        }

        // deferred x(s+1) store into own buffer pn (x region; read locally only)
        if (do_pref) {
            __half* abf = (__half*)Ab[pn];
            abf[so0] = __float2half(xv0);
            abf[so1] = __float2half(xv1);
            if (px2) abf[so2] = __float2half(xv2);
        }
        __syncthreads();   // hstage complete; Ab[p] reads complete

        // signal my producers: buffer p fully consumed
        if (tid == 0) {
            for (int r = 0; r < nprod; ++r) mbar_arrive_remote(okA[p], (unsigned)r);
        }

        // producer: wait permission, write h slice into consumers' Ab[pn], arrive full
        if (writer) {
            if (s >= 1) mbar_wait(okA[pn], ph_ok[pn]);
            if (compute) {
#pragma unroll
                for (int k2 = 0; k2 < 2; ++k2) {
                    int chunk = k2 * 32 + lane;
                    int row = chunk >> 2, c4 = chunk & 3;
                    uint4 v = *reinterpret_cast<const uint4*>(&hstage[row][c4 * 8]);
                    uint4* dst = (uint4*)cl.map_shared_rank(
                        (void*)&Ab[pn][row][doff + c4 * 8], warp);
                    *dst = v;
                }
            }
            __syncwarp();
            if (lane == 0) {
                asm volatile("fence.acq_rel.cluster;" ::: "memory");
                mbar_arrive_remote(fullA[pn], (unsigned)warp);
            }
        }
        if (s >= 1) ph_ok[pn] ^= 1;
        __syncthreads();   // hstage safe to overwrite next superstep
    }

    cl.sync();   // no CTA exits while peers' remote ops may be in flight

    if (!is_l0) {
        int hb = lrank * 32;
        g_h2[(slotbase + m_row) * HH + hb + hj0] = hreg[0];
        g_h2[(slotbase + m_row) * HH + hb + hj1] = hreg[1];
    }
}

// ---------------- K3: LayerNorm + Linear head ----------------
__global__ void head_kernel(const float* __restrict__ lng, const float* __restrict__ lnb,
                            const float* __restrict__ fw, const float* __restrict__ fb,
                            float* __restrict__ out)
{
    int gm = blockIdx.x;
    int tid = threadIdx.x;       // 128 threads
    int bidx = g_order[gm];
    float v = g_h2[gm * HH + tid];
    float s = v, s2 = v * v;
#pragma unroll
    for (int o = 16; o; o >>= 1) {
        s  += __shfl_xor_sync(0xffffffffu, s, o);
        s2 += __shfl_xor_sync(0xffffffffu, s2, o);
    }
    __shared__ float rs[4], rs2[4], hn[HH];
    if ((tid & 31) == 0) { rs[tid >> 5] = s; rs2[tid >> 5] = s2; }
    __syncthreads();
    float mu  = (rs[0] + rs[1] + rs[2] + rs[3]) * (1.0f / HH);
    float var = (rs2[0] + rs2[1] + rs2[2] + rs2[3]) * (1.0f / HH) - mu * mu;
    hn[tid] = (v - mu) * rsqrtf(var + 1e-5f) * lng[tid] + lnb[tid];
    __syncthreads();
    if (tid < CC) {
        float acc = fb[tid];
#pragma unroll 8
        for (int j = 0; j < HH; ++j) acc += fw[tid * HH + j] * hn[j];
        out[bidx * CC + tid] = acc;
    }
}

// ---------------- launch ----------------
extern "C" void kernel_launch(void* const* d_in, const int* in_sizes, int n_in,
                              void* d_out, int out_size)
{
    (void)in_sizes; (void)n_in; (void)out_size;
    const float* x     = (const float*)d_in[0];
    const int*   len   = (const int*)  d_in[1];
    const float* Wih0  = (const float*)d_in[2];
    const float* Whh0  = (const float*)d_in[3];
    const float* bih0  = (const float*)d_in[4];
    const float* bhh0  = (const float*)d_in[5];
    const float* Wih1  = (const float*)d_in[6];
    const float* Whh1  = (const float*)d_in[7];
    const float* bih1  = (const float*)d_in[8];
    const float* bhh1  = (const float*)d_in[9];
    const float* lng   = (const float*)d_in[10];
    const float* lnb   = (const float*)d_in[11];
    const float* fcw   = (const float*)d_in[12];
    const float* fcb   = (const float*)d_in[13];
    float* out = (float*)d_out;

    sort_kernel<<<1, BB>>>(len);
    lstm_fused<<<128, 256>>>(x, Wih0, Whh0, bih0, bhh0, Wih1, Whh1, bih1, bhh1);
    head_kernel<<<BB, 128>>>(lng, lnb, fcw, fcb, out);
}

// round 6
// speedup vs baseline: 2.2650x; 2.2650x over previous
#include <cuda_runtime.h>
#include <cuda_fp16.h>
#include <cooperative_groups.h>

namespace cg = cooperative_groups;

#define BB 256
#define TT 2048
#define DD 40
#define HH 128
#define CC 35

// A-operand row stride (halves): 528B; 528 mod 128 = 16 -> conflict-free ldmatrix.
#define AK 264
#define KT0 11   // layer0: [x(40)->48 | h1(128)] K=176
#define KT1 16   // layer1: [h1(128) | h2(128)]   K=256

__device__ int   g_order[BB];
__device__ int   g_slen[BB];
__device__ float g_h2[BB * HH];

// ---------------- mma / ldsm / activations ----------------
__device__ __forceinline__ void mma16816(float* d, const unsigned* a, const unsigned* b) {
    asm volatile(
        "mma.sync.aligned.m16n8k16.row.col.f32.f16.f16.f32 "
        "{%0,%1,%2,%3}, {%4,%5,%6,%7}, {%8,%9}, {%0,%1,%2,%3};\n"
        : "+f"(d[0]), "+f"(d[1]), "+f"(d[2]), "+f"(d[3])
        : "r"(a[0]), "r"(a[1]), "r"(a[2]), "r"(a[3]), "r"(b[0]), "r"(b[1]));
}
__device__ __forceinline__ void ldsmx4(unsigned* a, const __half* p) {
    unsigned addr = (unsigned)__cvta_generic_to_shared(p);
    asm volatile("ldmatrix.sync.aligned.m8n8.x4.shared.b16 {%0,%1,%2,%3}, [%4];"
                 : "=r"(a[0]), "=r"(a[1]), "=r"(a[2]), "=r"(a[3])
                 : "r"(addr));
}
__device__ __forceinline__ float tanha(float x) {
    float y; asm("tanh.approx.f32 %0, %1;" : "=f"(y) : "f"(x)); return y;
}
__device__ __forceinline__ float sigf(float x) { return fmaf(0.5f, tanha(0.5f * x), 0.5f); }

#define CLUSTER_ARRIVE() asm volatile("barrier.cluster.arrive.aligned;" ::: "memory")
#define CLUSTER_WAIT()   asm volatile("barrier.cluster.wait.aligned;"   ::: "memory")

// ---------------- K0: rank-sort lengths (descending, stable) ----------------
__global__ void sort_kernel(const int* __restrict__ length) {
    __shared__ int len[BB];
    int i = threadIdx.x;
    len[i] = length[i];
    __syncthreads();
    int li = len[i];
    int rank = 0;
    for (int j = 0; j < BB; ++j) {
        int lj = len[j];
        rank += (lj > li) || (lj == li && j < i);
    }
    g_order[rank] = i;
    g_slen[rank]  = li;
}

// ---------------- K1: fused 2-layer LSTM ----------------
// 16 clusters of 8 CTAs. Ranks 0-3: layer 0; ranks 4-7: layer 1 (one step behind).
// Each CTA: M=16 rows, N=128 gate cols (gate-interleaved: n -> gate n&3, h (n>>2)),
// 128 threads = 4 warps x 4 n-tiles. Weights in registers. One split cluster
// barrier per superstep; h exchanged via DSMEM stores before the arrive.
__global__ void __cluster_dims__(8, 1, 1) __launch_bounds__(128, 1)
lstm_fused(const float* __restrict__ x,
           const float* __restrict__ Wih0, const float* __restrict__ Whh0,
           const float* __restrict__ bih0, const float* __restrict__ bhh0,
           const float* __restrict__ Wih1, const float* __restrict__ Whh1,
           const float* __restrict__ bih1, const float* __restrict__ bhh1)
{
    cg::cluster_group cl = cg::this_cluster();
    const int rank   = (int)cl.block_rank();
    const bool is_l0 = (rank < 4);
    const int lrank  = rank & 3;
    const int group  = blockIdx.x >> 3;
    const int slotbase = group * 16;
    const int tid  = threadIdx.x;
    const int warp = tid >> 5, lane = tid & 31;

    __shared__ __align__(16) __half Ab[2][16][AK];
    __shared__ __align__(16) __half hstage[16][32];
    __shared__ float bsm[128];
    __shared__ int   slenS[16], morder[16];

    const float* Wih = is_l0 ? Wih0 : Wih1;
    const float* Whh = is_l0 ? Whh0 : Whh1;
    const float* bih = is_l0 ? bih0 : bih1;
    const float* bhh = is_l0 ? bhh0 : bhh1;
    const int KX  = is_l0 ? 48 : 128;
    const int DIN = is_l0 ? DD : HH;

    // ---- weights -> register fragments (4 n-tiles per warp) ----
    unsigned wf[4][16][2];
#pragma unroll
    for (int nt = 0; nt < 4; ++nt) {
        int n_local = warp * 32 + nt * 8 + (lane >> 2);
        int grow = (n_local & 3) * 128 + lrank * 32 + (n_local >> 2);
        for (int kt = 0; kt < 16; ++kt) {
            if (kt >= (is_l0 ? KT0 : KT1)) break;
#pragma unroll
            for (int f = 0; f < 2; ++f) {
                int k0 = kt * 16 + (lane & 3) * 2 + f * 8;
                int k1 = k0 + 1;
                float v0 = (k0 < KX) ? ((k0 < DIN) ? Wih[grow * DIN + k0] : 0.0f)
                                     : Whh[grow * HH + (k0 - KX)];
                float v1 = (k1 < KX) ? ((k1 < DIN) ? Wih[grow * DIN + k1] : 0.0f)
                                     : Whh[grow * HH + (k1 - KX)];
                __half2 hv = __floats2half2_rn(v0, v1);
                wf[nt][kt][f] = *reinterpret_cast<unsigned*>(&hv);
            }
        }
    }
    {
        int grow = (tid & 3) * 128 + lrank * 32 + (tid >> 2);
        bsm[tid] = bih[grow] + bhh[grow];
    }
    if (tid < 16) {
        slenS[tid]  = g_slen[slotbase + tid];
        morder[tid] = g_order[slotbase + tid];
    }
    for (int i = tid; i < 2 * 16 * AK; i += 128) ((__half*)Ab)[i] = __float2half(0.0f);
    __syncthreads();
    const int maxlen = slenS[0];

    // bias -> registers
    float bias0[4], bias1[4];
#pragma unroll
    for (int nt = 0; nt < 4; ++nt) {
        int c0 = warp * 32 + nt * 8 + 2 * (lane & 3);
        bias0[nt] = bsm[c0]; bias1[nt] = bsm[c0 + 1];
    }

    // per-thread cell ownership: row m_row, 4 h-cols hj(nt) = warp*8 + nt*2 + ((lane&3)>>1)
    const int m_row = (lane >> 2) + ((lane & 1) << 3);
    const int myslen = slenS[m_row];
    const int hjb = warp * 8 + ((lane & 3) >> 1);
    float creg[4] = {0.f, 0.f, 0.f, 0.f};
    float hreg[4] = {0.f, 0.f, 0.f, 0.f};

    // x prefetch: 640 elems = 5 per thread, thread-constant pointers
    const float* px[5];
    int so[5];
    if (is_l0) {
#pragma unroll
        for (int k = 0; k < 5; ++k) {
            int i = tid + k * 128;
            int m = i / DD, d = i - m * DD;
            px[k] = x + (size_t)morder[m] * TT * DD + d + DD;   // x(s+1)
            so[k] = m * AK + d;
        }
        for (int i = tid; i < 16 * DD; i += 128) {              // x(0) -> buffer 0
            int m = i / DD, d = i - m * DD;
            Ab[0][m][d] = __float2half(x[((size_t)morder[m] * TT) * DD + d]);
        }
    }
    __syncthreads();

    const __half* arowP[2] = { &Ab[0][lane & 15][(lane >> 4) << 3],
                               &Ab[1][lane & 15][(lane >> 4) << 3] };
    // broadcast destinations: warp w -> rank w (l0 consumers, h1 col 48+)
    //                         and rank w+4 (l1: h1 col 0+ / h2 col 128+)
    const int doffA = 48 + lrank * 32;                 // into l0 consumers (l0 producer only)
    const int doffB = (is_l0 ? 0 : 128) + lrank * 32;  // into l1 consumers

    CLUSTER_ARRIVE();   // init + buffer0 published

    for (int s = 0; s <= maxlen; ++s) {
        const int p = s & 1, pn = p ^ 1;
        const bool compute = is_l0 ? (s < maxlen) : (s >= 1);
        const bool do_pref = is_l0 && (s + 1 < maxlen);

        // issue x(s+1) loads before the barrier wait (latency overlap)
        float xv[5];
        if (do_pref) {
#pragma unroll
            for (int k = 0; k < 5; ++k) { xv[k] = *px[k]; px[k] += DD; }
        }

        CLUSTER_WAIT();   // peers' h slices for buffer p have landed

        if (compute) {
            float acc[4][4];
#pragma unroll
            for (int nt = 0; nt < 4; ++nt) {
                acc[nt][0] = bias0[nt]; acc[nt][1] = bias1[nt];
                acc[nt][2] = bias0[nt]; acc[nt][3] = bias1[nt];
            }
            const __half* arow = arowP[p];
            if (is_l0) {
#pragma unroll
                for (int kt = 0; kt < KT0; ++kt) {
                    unsigned a[4];
                    ldsmx4(a, arow + kt * 16);
                    mma16816(acc[0], a, wf[0][kt]); mma16816(acc[1], a, wf[1][kt]);
                    mma16816(acc[2], a, wf[2][kt]); mma16816(acc[3], a, wf[3][kt]);
                }
            } else {
#pragma unroll
                for (int kt = 0; kt < KT1; ++kt) {
                    unsigned a[4];
                    ldsmx4(a, arow + kt * 16);
                    mma16816(acc[0], a, wf[0][kt]); mma16816(acc[1], a, wf[1][kt]);
                    mma16816(acc[2], a, wf[2][kt]); mma16816(acc[3], a, wf[3][kt]);
                }
            }
            const int t_eff = is_l0 ? s : (s - 1);
            const bool act = t_eff < myslen;
            const int sel = (lane & 1) * 2;
#pragma unroll
            for (int nt = 0; nt < 4; ++nt) {
                float o0 = __shfl_xor_sync(0xffffffffu, acc[nt][0], 1);
                float o1 = __shfl_xor_sync(0xffffffffu, acc[nt][1], 1);
                float o2 = __shfl_xor_sync(0xffffffffu, acc[nt][2], 1);
                float o3 = __shfl_xor_sync(0xffffffffu, acc[nt][3], 1);
                float iv, fv, gv, ov;
                if ((lane & 1) == 0) {
                    iv = acc[nt][sel]; fv = acc[nt][sel + 1];
                    gv = (sel == 0) ? o0 : o2; ov = (sel == 0) ? o1 : o3;
                } else {
                    iv = (sel == 0) ? o0 : o2; fv = (sel == 0) ? o1 : o3;
                    gv = acc[nt][sel]; ov = acc[nt][sel + 1];
                }
                float hn;
                if (act) {
                    float gi = sigf(iv), gf = sigf(fv), gg = tanha(gv), go = sigf(ov);
                    float cn = gf * creg[nt] + gi * gg;
                    creg[nt] = cn;
                    hn = go * tanha(cn);
                    hreg[nt] = hn;
                } else {
                    hn = hreg[nt];
                }
                hstage[m_row][hjb + nt * 2] = __float2half(hn);
            }
        }

        if (do_pref) {
            __half* abf = (__half*)Ab[pn];
#pragma unroll
            for (int k = 0; k < 5; ++k) abf[so[k]] = __float2half(xv[k]);
        }
        __syncthreads();   // hstage complete; Ab[p] reads complete

        // ---- DSMEM broadcast of h slice into buffer pn ----
        if (compute) {
#pragma unroll
            for (int k2 = 0; k2 < 2; ++k2) {
                int chunk = k2 * 32 + lane;
                int row = chunk >> 2, c4 = chunk & 3;
                uint4 v = *reinterpret_cast<const uint4*>(&hstage[row][c4 * 8]);
                if (is_l0) {
                    uint4* d0 = (uint4*)cl.map_shared_rank(
                        (void*)&Ab[pn][row][doffA + c4 * 8], warp);
                    *d0 = v;
                }
                uint4* d1 = (uint4*)cl.map_shared_rank(
                    (void*)&Ab[pn][row][doffB + c4 * 8], warp + 4);
                *d1 = v;
            }
        }
        CLUSTER_ARRIVE();   // release: h writes visible before consumers' wait
    }

    CLUSTER_WAIT();   // pair final arrive; peers done writing into my smem

    if (!is_l0) {
        int hb = lrank * 32;
#pragma unroll
        for (int nt = 0; nt < 4; ++nt)
            g_h2[(slotbase + m_row) * HH + hb + hjb + nt * 2] = hreg[nt];
    }
}

// ---------------- K3: LayerNorm + Linear head ----------------
__global__ void head_kernel(const float* __restrict__ lng, const float* __restrict__ lnb,
                            const float* __restrict__ fw, const float* __restrict__ fb,
                            float* __restrict__ out)
{
    int gm = blockIdx.x;
    int tid = threadIdx.x;       // 128 threads
    int bidx = g_order[gm];
    float v = g_h2[gm * HH + tid];
    float s = v, s2 = v * v;
#pragma unroll
    for (int o = 16; o; o >>= 1) {
        s  += __shfl_xor_sync(0xffffffffu, s, o);
        s2 += __shfl_xor_sync(0xffffffffu, s2, o);
    }
    __shared__ float rs[4], rs2[4], hn[HH];
    if ((tid & 31) == 0) { rs[tid >> 5] = s; rs2[tid >> 5] = s2; }
    __syncthreads();
    float mu  = (rs[0] + rs[1] + rs[2] + rs[3]) * (1.0f / HH);
    float var = (rs2[0] + rs2[1] + rs2[2] + rs2[3]) * (1.0f / HH) - mu * mu;
    hn[tid] = (v - mu) * rsqrtf(var + 1e-5f) * lng[tid] + lnb[tid];
    __syncthreads();
    if (tid < CC) {
        float acc = fb[tid];
#pragma unroll 8
        for (int j = 0; j < HH; ++j) acc += fw[tid * HH + j] * hn[j];
        out[bidx * CC + tid] = acc;
    }
}

// ---------------- launch ----------------
extern "C" void kernel_launch(void* const* d_in, const int* in_sizes, int n_in,
                              void* d_out, int out_size)
{
    (void)in_sizes; (void)n_in; (void)out_size;
    const float* x     = (const float*)d_in[0];
    const int*   len   = (const int*)  d_in[1];
    const float* Wih0  = (const float*)d_in[2];
    const float* Whh0  = (const float*)d_in[3];
    const float* bih0  = (const float*)d_in[4];
    const float* bhh0  = (const float*)d_in[5];
    const float* Wih1  = (const float*)d_in[6];
    const float* Whh1  = (const float*)d_in[7];
    const float* bih1  = (const float*)d_in[8];
    const float* bhh1  = (const float*)d_in[9];
    const float* lng   = (const float*)d_in[10];
    const float* lnb   = (const float*)d_in[11];
    const float* fcw   = (const float*)d_in[12];
    const float* fcb   = (const float*)d_in[13];
    float* out = (float*)d_out;

    sort_kernel<<<1, BB>>>(len);
    lstm_fused<<<128, 128>>>(x, Wih0, Whh0, bih0, bhh0, Wih1, Whh1, bih1, bhh1);
    head_kernel<<<BB, 128>>>(lng, lnb, fcw, fcb, out);
}

// round 7
// speedup vs baseline: 2.3926x; 1.0563x over previous
#include <cuda_runtime.h>
#include <cuda_fp16.h>
#include <cooperative_groups.h>

namespace cg = cooperative_groups;

#define BB 256
#define TT 2048
#define DD 40
#define HH 128
#define CC 35

// A-operand row stride (halves): 528B; 528 mod 128 = 16 -> conflict-free ldmatrix.
#define AK 264
#define KT0 11   // layer0: [x(40)->48 | h1(128)] K=176 ; pre kt 0..2, crit kt 3..10
#define KT1 16   // layer1: [h1(128) | h2(128)]   K=256 ; pre kt 0..7, crit kt 8..15

__device__ int   g_order[BB];
__device__ int   g_slen[BB];
__device__ float g_h2[BB * HH];

// ---------------- mma / ldsm / activations ----------------
__device__ __forceinline__ void mma16816(float* d, const unsigned* a, const unsigned* b) {
    asm volatile(
        "mma.sync.aligned.m16n8k16.row.col.f32.f16.f16.f32 "
        "{%0,%1,%2,%3}, {%4,%5,%6,%7}, {%8,%9}, {%0,%1,%2,%3};\n"
        : "+f"(d[0]), "+f"(d[1]), "+f"(d[2]), "+f"(d[3])
        : "r"(a[0]), "r"(a[1]), "r"(a[2]), "r"(a[3]), "r"(b[0]), "r"(b[1]));
}
__device__ __forceinline__ void ldsmx4(unsigned* a, const __half* p) {
    unsigned addr = (unsigned)__cvta_generic_to_shared(p);
    asm volatile("ldmatrix.sync.aligned.m8n8.x4.shared.b16 {%0,%1,%2,%3}, [%4];"
                 : "=r"(a[0]), "=r"(a[1]), "=r"(a[2]), "=r"(a[3])
                 : "r"(addr));
}
__device__ __forceinline__ float tanha(float x) {
    float y; asm("tanh.approx.f32 %0, %1;" : "=f"(y) : "f"(x)); return y;
}
__device__ __forceinline__ float sigf(float x) { return fmaf(0.5f, tanha(0.5f * x), 0.5f); }

#define CLUSTER_ARRIVE() asm volatile("barrier.cluster.arrive.aligned;" ::: "memory")
#define CLUSTER_WAIT()   asm volatile("barrier.cluster.wait.aligned;"   ::: "memory")

// ---------------- K0: rank-sort lengths (descending, stable) ----------------
__global__ void sort_kernel(const int* __restrict__ length) {
    __shared__ int len[BB];
    int i = threadIdx.x;
    len[i] = length[i];
    __syncthreads();
    int li = len[i];
    int rank = 0;
    for (int j = 0; j < BB; ++j) {
        int lj = len[j];
        rank += (lj > li) || (lj == li && j < i);
    }
    g_order[rank] = i;
    g_slen[rank]  = li;
}

// ---------------- K1: fused 2-layer LSTM, precomputed off-recurrence MMA ----------
// 16 clusters of 8 CTAs. Ranks 0-3: layer 0 (lag 0). Ranks 4-7: layer 1 (lag 2).
// Each CTA: M=16 rows, N=128 gate cols (gate-interleaved), 128 thr = 4 warps x 4 nt.
// Per superstep: only the recurrent half of the MMA (8 k-tiles) runs after the
// cluster wait; the feed-forward half (x-part / h1-part) is precomputed into the
// accumulators right after the previous arrive, overlapping the barrier latency.
// l0: double-buffered A [x|h1]; l1: triple-buffered A [h1|h2] (lag-2 slack).
__global__ void __cluster_dims__(8, 1, 1) __launch_bounds__(128, 1)
lstm_fused(const float* __restrict__ x,
           const float* __restrict__ Wih0, const float* __restrict__ Whh0,
           const float* __restrict__ bih0, const float* __restrict__ bhh0,
           const float* __restrict__ Wih1, const float* __restrict__ Whh1,
           const float* __restrict__ bih1, const float* __restrict__ bhh1)
{
    cg::cluster_group cl = cg::this_cluster();
    const int rank   = (int)cl.block_rank();
    const bool is_l0 = (rank < 4);
    const int lrank  = rank & 3;
    const int group  = blockIdx.x >> 3;
    const int slotbase = group * 16;
    const int tid  = threadIdx.x;
    const int warp = tid >> 5, lane = tid & 31;

    __shared__ __align__(16) __half A0[2][16][AK];   // layer-0 CTAs
    __shared__ __align__(16) __half A1[3][16][AK];   // layer-1 CTAs
    __shared__ __align__(16) __half hstage[16][32];
    __shared__ float bsm[128];
    __shared__ int   slenS[16], morder[16];

    const float* Wih = is_l0 ? Wih0 : Wih1;
    const float* Whh = is_l0 ? Whh0 : Whh1;
    const float* bih = is_l0 ? bih0 : bih1;
    const float* bhh = is_l0 ? bhh0 : bhh1;
    const int KX  = is_l0 ? 48 : 128;
    const int DIN = is_l0 ? DD : HH;

    // ---- weights -> register fragments (4 n-tiles per warp, gate-interleaved) ----
    unsigned wf[4][16][2];
#pragma unroll
    for (int nt = 0; nt < 4; ++nt) {
        int n_local = warp * 32 + nt * 8 + (lane >> 2);
        int grow = (n_local & 3) * 128 + lrank * 32 + (n_local >> 2);
        for (int kt = 0; kt < 16; ++kt) {
            if (kt >= (is_l0 ? KT0 : KT1)) break;
#pragma unroll
            for (int f = 0; f < 2; ++f) {
                int k0 = kt * 16 + (lane & 3) * 2 + f * 8;
                int k1 = k0 + 1;
                float v0 = (k0 < KX) ? ((k0 < DIN) ? Wih[grow * DIN + k0] : 0.0f)
                                     : Whh[grow * HH + (k0 - KX)];
                float v1 = (k1 < KX) ? ((k1 < DIN) ? Wih[grow * DIN + k1] : 0.0f)
                                     : Whh[grow * HH + (k1 - KX)];
                __half2 hv = __floats2half2_rn(v0, v1);
                wf[nt][kt][f] = *reinterpret_cast<unsigned*>(&hv);
            }
        }
    }
    {
        int grow = (tid & 3) * 128 + lrank * 32 + (tid >> 2);
        bsm[tid] = bih[grow] + bhh[grow];
    }
    if (tid < 16) {
        slenS[tid]  = g_slen[slotbase + tid];
        morder[tid] = g_order[slotbase + tid];
    }
    for (int i = tid; i < 2 * 16 * AK; i += 128) ((__half*)A0)[i] = __float2half(0.0f);
    for (int i = tid; i < 3 * 16 * AK; i += 128) ((__half*)A1)[i] = __float2half(0.0f);
    __syncthreads();
    const int maxlen = slenS[0];

    float bias0[4], bias1[4];
#pragma unroll
    for (int nt = 0; nt < 4; ++nt) {
        int c0 = warp * 32 + nt * 8 + 2 * (lane & 3);
        bias0[nt] = bsm[c0]; bias1[nt] = bsm[c0 + 1];
    }

    // per-thread cell ownership
    const int m_row = (lane >> 2) + ((lane & 1) << 3);
    const int myslen = slenS[m_row];
    const int hjb = warp * 8 + ((lane & 3) >> 1);
    float creg[4] = {0.f, 0.f, 0.f, 0.f};
    float hreg[4] = {0.f, 0.f, 0.f, 0.f};

    // x prefetch: 640 elems = 5 per thread, thread-constant pointers
    const float* px[5];
    int so[5];
    if (is_l0) {
#pragma unroll
        for (int k = 0; k < 5; ++k) {
            int i = tid + k * 128;
            int m = i / DD, d = i - m * DD;
            px[k] = x + (size_t)morder[m] * TT * DD + d + DD;   // x(s+1)
            so[k] = m * AK + d;
        }
        for (int i = tid; i < 16 * DD; i += 128) {              // x(0) -> buffer 0
            int m = i / DD, d = i - m * DD;
            A0[0][m][d] = __float2half(x[((size_t)morder[m] * TT) * DD + d]);
        }
    }
    __syncthreads();

    const int lrowoff = (lane & 15);
    const int lcoloff = (lane >> 4) << 3;

    float acc[4][4];

    // pre-loop precompute for superstep 0 (l0 only: bias + x(0)-part)
    if (is_l0) {
#pragma unroll
        for (int nt = 0; nt < 4; ++nt) {
            acc[nt][0] = bias0[nt]; acc[nt][1] = bias1[nt];
            acc[nt][2] = bias0[nt]; acc[nt][3] = bias1[nt];
        }
        const __half* ar = &A0[0][lrowoff][lcoloff];
#pragma unroll
        for (int kt = 0; kt < 3; ++kt) {
            unsigned a[4];
            ldsmx4(a, ar + kt * 16);
            mma16816(acc[0], a, wf[0][kt]); mma16816(acc[1], a, wf[1][kt]);
            mma16816(acc[2], a, wf[2][kt]); mma16816(acc[3], a, wf[3][kt]);
        }
    }

    CLUSTER_ARRIVE();   // zero-init + buffer0 published

    for (int s = 0; s <= maxlen + 1; ++s) {
        const int p2 = s & 1;
        const int b3 = s % 3;
        const bool compute = is_l0 ? (s < maxlen) : (s >= 2);
        const bool do_pref = is_l0 && (s + 1 < maxlen);

        // issue x(s+1) loads before the barrier wait (latency overlap)
        float xv[5];
        if (do_pref) {
#pragma unroll
            for (int k = 0; k < 5; ++k) { xv[k] = *px[k]; px[k] += DD; }
        }

        CLUSTER_WAIT();   // recurrent operands for this superstep have landed

        if (compute) {
            // ---- critical (recurrent) MMA: 8 k-tiles ----
            if (is_l0) {
                const __half* ar = &A0[p2][lrowoff][lcoloff];
#pragma unroll
                for (int kt = 3; kt < 11; ++kt) {
                    unsigned a[4];
                    ldsmx4(a, ar + kt * 16);
                    mma16816(acc[0], a, wf[0][kt]); mma16816(acc[1], a, wf[1][kt]);
                    mma16816(acc[2], a, wf[2][kt]); mma16816(acc[3], a, wf[3][kt]);
                }
            } else {
                const __half* ar = &A1[b3][lrowoff][lcoloff];
#pragma unroll
                for (int kt = 8; kt < 16; ++kt) {
                    unsigned a[4];
                    ldsmx4(a, ar + kt * 16);
                    mma16816(acc[0], a, wf[0][kt]); mma16816(acc[1], a, wf[1][kt]);
                    mma16816(acc[2], a, wf[2][kt]); mma16816(acc[3], a, wf[3][kt]);
                }
            }
            const int t_eff = is_l0 ? s : (s - 2);
            const bool act = t_eff < myslen;
            const int sel = (lane & 1) * 2;
#pragma unroll
            for (int nt = 0; nt < 4; ++nt) {
                float o0 = __shfl_xor_sync(0xffffffffu, acc[nt][0], 1);
                float o1 = __shfl_xor_sync(0xffffffffu, acc[nt][1], 1);
                float o2 = __shfl_xor_sync(0xffffffffu, acc[nt][2], 1);
                float o3 = __shfl_xor_sync(0xffffffffu, acc[nt][3], 1);
                float iv, fv, gv, ov;
                if ((lane & 1) == 0) {
                    iv = acc[nt][sel]; fv = acc[nt][sel + 1];
                    gv = (sel == 0) ? o0 : o2; ov = (sel == 0) ? o1 : o3;
                } else {
                    iv = (sel == 0) ? o0 : o2; fv = (sel == 0) ? o1 : o3;
                    gv = acc[nt][sel]; ov = acc[nt][sel + 1];
                }
                float hn;
                if (act) {
                    float gi = sigf(iv), gf = sigf(fv), gg = tanha(gv), go = sigf(ov);
                    float cn = gf * creg[nt] + gi * gg;
                    creg[nt] = cn;
                    hn = go * tanha(cn);
                    hreg[nt] = hn;
                } else {
                    hn = hreg[nt];
                }
                hstage[m_row][hjb + nt * 2] = __float2half(hn);
            }
        }

        // deferred x(s+1) store into own buffer (s+1)&1 x-region
        if (do_pref) {
            __half* abf = (__half*)A0[p2 ^ 1];
#pragma unroll
            for (int k = 0; k < 5; ++k) abf[so[k]] = __float2half(xv[k]);
        }
        __syncthreads();   // hstage complete; this buffer's reads complete

        // ---- DSMEM broadcast of h slice (warp w -> rank w / w+4) ----
        if (compute) {
            const int bn2 = (s + 1) & 1;          // l0-consumer buffer
            const int bh1 = (s + 2) % 3;          // l1-consumer h1 buffer (from l0)
            const int bh2 = (s + 1) % 3;          // l1-consumer h2 buffer (from l1)
#pragma unroll
            for (int k2 = 0; k2 < 2; ++k2) {
                int chunk = k2 * 32 + lane;
                int row = chunk >> 2, c4 = chunk & 3;
                uint4 v = *reinterpret_cast<const uint4*>(&hstage[row][c4 * 8]);
                if (is_l0) {
                    uint4* d0 = (uint4*)cl.map_shared_rank(
                        (void*)&A0[bn2][row][48 + lrank * 32 + c4 * 8], warp);
                    *d0 = v;
                    uint4* d1 = (uint4*)cl.map_shared_rank(
                        (void*)&A1[bh1][row][lrank * 32 + c4 * 8], warp + 4);
                    *d1 = v;
                } else {
                    uint4* d1 = (uint4*)cl.map_shared_rank(
                        (void*)&A1[bh2][row][128 + lrank * 32 + c4 * 8], warp + 4);
                    *d1 = v;
                }
            }
        }
        CLUSTER_ARRIVE();   // release: h writes ordered before consumers' wait

        // ---- precompute next superstep's feed-forward MMA (off critical path) ----
        if (is_l0) {
            if (s + 1 < maxlen) {
#pragma unroll
                for (int nt = 0; nt < 4; ++nt) {
                    acc[nt][0] = bias0[nt]; acc[nt][1] = bias1[nt];
                    acc[nt][2] = bias0[nt]; acc[nt][3] = bias1[nt];
                }
                const __half* ar = &A0[p2 ^ 1][lrowoff][lcoloff];
#pragma unroll
                for (int kt = 0; kt < 3; ++kt) {
                    unsigned a[4];
                    ldsmx4(a, ar + kt * 16);
                    mma16816(acc[0], a, wf[0][kt]); mma16816(acc[1], a, wf[1][kt]);
                    mma16816(acc[2], a, wf[2][kt]); mma16816(acc[3], a, wf[3][kt]);
                }
            }
        } else {
            if (s + 1 >= 2 && s <= maxlen) {
#pragma unroll
                for (int nt = 0; nt < 4; ++nt) {
                    acc[nt][0] = bias0[nt]; acc[nt][1] = bias1[nt];
                    acc[nt][2] = bias0[nt]; acc[nt][3] = bias1[nt];
                }
                const __half* ar = &A1[(s + 1) % 3][lrowoff][lcoloff];
#pragma unroll
                for (int kt = 0; kt < 8; ++kt) {
                    unsigned a[4];
                    ldsmx4(a, ar + kt * 16);
                    mma16816(acc[0], a, wf[0][kt]); mma16816(acc[1], a, wf[1][kt]);
                    mma16816(acc[2], a, wf[2][kt]); mma16816(acc[3], a, wf[3][kt]);
                }
            }
        }
    }

    CLUSTER_WAIT();   // pair final arrive; peers done writing into my smem

    if (!is_l0) {
        int hb = lrank * 32;
#pragma unroll
        for (int nt = 0; nt < 4; ++nt)
            g_h2[(slotbase + m_row) * HH + hb + hjb + nt * 2] = hreg[nt];
    }
}

// ---------------- K3: LayerNorm + Linear head ----------------
__global__ void head_kernel(const float* __restrict__ lng, const float* __restrict__ lnb,
                            const float* __restrict__ fw, const float* __restrict__ fb,
                            float* __restrict__ out)
{
    int gm = blockIdx.x;
    int tid = threadIdx.x;       // 128 threads
    int bidx = g_order[gm];
    float v = g_h2[gm * HH + tid];
    float s = v, s2 = v * v;
#pragma unroll
    for (int o = 16; o; o >>= 1) {
        s  += __shfl_xor_sync(0xffffffffu, s, o);
        s2 += __shfl_xor_sync(0xffffffffu, s2, o);
    }
    __shared__ float rs[4], rs2[4], hn[HH];
    if ((tid & 31) == 0) { rs[tid >> 5] = s; rs2[tid >> 5] = s2; }
    __syncthreads();
    float mu  = (rs[0] + rs[1] + rs[2] + rs[3]) * (1.0f / HH);
    float var = (rs2[0] + rs2[1] + rs2[2] + rs2[3]) * (1.0f / HH) - mu * mu;
    hn[tid] = (v - mu) * rsqrtf(var + 1e-5f) * lng[tid] + lnb[tid];
    __syncthreads();
    if (tid < CC) {
        float acc = fb[tid];
#pragma unroll 8
        for (int j = 0; j < HH; ++j) acc += fw[tid * HH + j] * hn[j];
        out[bidx * CC + tid] = acc;
    }
}

// ---------------- launch ----------------
extern "C" void kernel_launch(void* const* d_in, const int* in_sizes, int n_in,
                              void* d_out, int out_size)
{
    (void)in_sizes; (void)n_in; (void)out_size;
    const float* x     = (const float*)d_in[0];
    const int*   len   = (const int*)  d_in[1];
    const float* Wih0  = (const float*)d_in[2];
    const float* Whh0  = (const float*)d_in[3];
    const float* bih0  = (const float*)d_in[4];
    const float* bhh0  = (const float*)d_in[5];
    const float* Wih1  = (const float*)d_in[6];
    const float* Whh1  = (const float*)d_in[7];
    const float* bih1  = (const float*)d_in[8];
    const float* bhh1  = (const float*)d_in[9];
    const float* lng   = (const float*)d_in[10];
    const float* lnb   = (const float*)d_in[11];
    const float* fcw   = (const float*)d_in[12];
    const float* fcb   = (const float*)d_in[13];
    float* out = (float*)d_out;

    sort_kernel<<<1, BB>>>(len);
    lstm_fused<<<128, 128>>>(x, Wih0, Whh0, bih0, bhh0, Wih1, Whh1, bih1, bhh1);
    head_kernel<<<BB, 128>>>(lng, lnb, fcw, fcb, out);
}